// round 2
// baseline (speedup 1.0000x reference)
#include <cuda_runtime.h>
#include <cstdint>
#include <math.h>

#define BB 64
#define AA 8400
#define CC 80
#define KK 300
#define HF 160
#define WF 160
#define NBINS 4096
#define CAP 4096
#define THRESH 0.25f

// scratch (no allocations allowed)
__device__ float g_scores[BB * AA];
__device__ float g_beta[BB * AA];
__device__ int   g_cls[BB * AA];

__global__ void phase1_kernel(const float4* __restrict__ boxes,
                              const float*  __restrict__ obj,
                              const float4* __restrict__ cls,
                              const float*  __restrict__ field) {
    int i = blockIdx.x * blockDim.x + threadIdx.x;
    if (i >= BB * AA) return;
    int b = i / AA;

    float4 bx = boxes[i];
    float x1 = bx.x, y1 = bx.y, x2 = bx.z, y2 = bx.w;

    // 3x3 bilinear pool of suspicion field
    const float* f = field + b * (HF * WF);
    float beta = 0.0f;
#pragma unroll
    for (int jy = 0; jy < 3; jy++) {
        float ty = (jy + 0.5f) * (1.0f / 3.0f);
        float ys = y1 + ty * (y2 - y1);
        float v = ys * 0.25f - 0.5f;
        v = fminf(fmaxf(v, 0.0f), (float)(HF - 1));
        float v0f = floorf(v);
        float fv = v - v0f;
        int v0 = (int)v0f;
        int v1 = min(v0 + 1, HF - 1);
#pragma unroll
        for (int jx = 0; jx < 3; jx++) {
            float tx = (jx + 0.5f) * (1.0f / 3.0f);
            float xs = x1 + tx * (x2 - x1);
            float u = xs * 0.25f - 0.5f;
            u = fminf(fmaxf(u, 0.0f), (float)(WF - 1));
            float u0f = floorf(u);
            float fu = u - u0f;
            int u0 = (int)u0f;
            int u1 = min(u0 + 1, WF - 1);
            float f00 = f[v0 * WF + u0];
            float f01 = f[v0 * WF + u1];
            float f10 = f[v1 * WF + u0];
            float f11 = f[v1 * WF + u1];
            beta += f00 * (1.0f - fv) * (1.0f - fu)
                  + f01 * (1.0f - fv) * fu
                  + f10 * fv * (1.0f - fu)
                  + f11 * fv * fu;
        }
    }
    beta *= (1.0f / 9.0f);

    float area = fmaxf(x2 - x1, 0.0f) * fmaxf(y2 - y1, 0.0f) * (1.0f / (640.0f * 640.0f));
    float bs = beta * ((area < 0.01f) ? 1.5f : 1.0f);

    // max + argmax over 80 class logits (sigmoid is monotone; shift is per-anchor const)
    const float4* cp = cls + (size_t)i * (CC / 4);
    float m = -1e30f;
    int am = 0;
#pragma unroll
    for (int j = 0; j < CC / 4; j++) {
        float4 v4 = cp[j];
        if (v4.x > m) { m = v4.x; am = 4 * j + 0; }
        if (v4.y > m) { m = v4.y; am = 4 * j + 1; }
        if (v4.z > m) { m = v4.z; am = 4 * j + 2; }
        if (v4.w > m) { m = v4.w; am = 4 * j + 3; }
    }

    float best_cls_score = 1.0f / (1.0f + expf(-(m - 0.5f * bs)));
    float sobj = 1.0f / (1.0f + expf(-(obj[i] - bs)));
    float comb = sobj * best_cls_score;

    g_scores[i] = comb;
    g_beta[i] = bs;
    g_cls[i] = am;
}

__global__ __launch_bounds__(1024) void phase2_kernel(const float4* __restrict__ boxes,
                                                      float* __restrict__ out) {
    int b = blockIdx.x;
    int tid = threadIdx.x;

    __shared__ unsigned long long s_cand[CAP];        // 32KB; first 16KB aliased as histogram
    unsigned int* s_hist = (unsigned int*)s_cand;
    __shared__ unsigned int s_warp[32];
    __shared__ int s_cutoff;
    __shared__ int s_cnt;
    __shared__ int s_M;
    __shared__ int s_P;

    // --- init + histogram ---
    for (int j = tid; j < NBINS; j += 1024) s_hist[j] = 0;
    if (tid == 0) { s_cutoff = 0; s_cnt = 0; }
    __syncthreads();

    const float* sc = g_scores + (size_t)b * AA;
    for (int a = tid; a < AA; a += 1024) {
        float s = sc[a];
        if (s >= THRESH) {
            int bin = (int)((s - THRESH) * (NBINS / 0.75f));
            bin = max(0, min(NBINS - 1, bin));
            atomicAdd(&s_hist[bin], 1u);
        }
    }
    __syncthreads();

    // --- suffix scan (count from top bin down), find cutoff bin for rank K ---
    {
        int g = 1023 - tid;                // thread 0 owns the highest bins
        int base = 4 * g;
        unsigned int c0 = s_hist[base + 3];
        unsigned int c1 = s_hist[base + 2];
        unsigned int c2 = s_hist[base + 1];
        unsigned int c3 = s_hist[base + 0];
        unsigned int i0 = c0;
        unsigned int i1 = i0 + c1;
        unsigned int i2 = i1 + c2;
        unsigned int i3 = i2 + c3;
        unsigned int ts = i3;

        unsigned int v = ts;
        int lane = tid & 31;
        int w = tid >> 5;
#pragma unroll
        for (int off = 1; off < 32; off <<= 1) {
            unsigned int n = __shfl_up_sync(0xffffffffu, v, off);
            if (lane >= off) v += n;
        }
        if (lane == 31) s_warp[w] = v;
        __syncthreads();
        if (tid < 32) {
            unsigned int x = s_warp[tid];
            unsigned int incl = x;
#pragma unroll
            for (int off = 1; off < 32; off <<= 1) {
                unsigned int n = __shfl_up_sync(0xffffffffu, incl, off);
                if (tid >= off) incl += n;
            }
            s_warp[tid] = incl - x;        // exclusive prefix of warp sums
        }
        __syncthreads();
        unsigned int texcl = s_warp[w] + (v - ts);   // count strictly above this thread's bins

        unsigned int cum0 = texcl + i0;    // inclusive from top for bin base+3
        unsigned int cum1 = texcl + i1;    // bin base+2
        unsigned int cum2 = texcl + i2;    // bin base+1
        unsigned int cum3 = texcl + i3;    // bin base+0
        if (cum0 >= KK) atomicMax(&s_cutoff, base + 3);
        if (cum1 >= KK) atomicMax(&s_cutoff, base + 2);
        if (cum2 >= KK) atomicMax(&s_cutoff, base + 1);
        if (cum3 >= KK) atomicMax(&s_cutoff, base + 0);
    }
    __syncthreads();
    int cutoff = s_cutoff;
    __syncthreads();   // everyone done reading hist before cand overwrites it

    // --- gather candidates (bin >= cutoff) as packed sort keys ---
    for (int a = tid; a < AA; a += 1024) {
        float s = sc[a];
        if (s >= THRESH) {
            int bin = (int)((s - THRESH) * (NBINS / 0.75f));
            bin = max(0, min(NBINS - 1, bin));
            if (bin >= cutoff) {
                int p = atomicAdd(&s_cnt, 1);
                if (p < CAP) {
                    unsigned long long key =
                        ((unsigned long long)__float_as_uint(s) << 32) |
                        (unsigned long long)(0xFFFFFFFFu ^ (unsigned int)a);
                    s_cand[p] = key;
                }
            }
        }
    }
    __syncthreads();
    if (tid == 0) {
        int M = min(s_cnt, CAP);
        int P = 1;
        while (P < M) P <<= 1;
        if (M == 0) P = 0;
        s_M = M;
        s_P = P;
    }
    __syncthreads();
    int M = s_M;
    int P = s_P;

    // pad to pow2 (pads have key 0 < any valid key)
    for (int j = M + tid; j < P; j += 1024) s_cand[j] = 0ull;
    __syncthreads();

    // --- bitonic sort, descending ---
    for (int k = 2; k <= P; k <<= 1) {
        for (int j = k >> 1; j > 0; j >>= 1) {
            for (int i = tid; i < P; i += 1024) {
                int l = i ^ j;
                if (l > i) {
                    unsigned long long a0 = s_cand[i];
                    unsigned long long a1 = s_cand[l];
                    bool dirDesc = ((i & k) == 0);
                    if ((a0 < a1) == dirDesc) {
                        s_cand[i] = a1;
                        s_cand[l] = a0;
                    }
                }
            }
            __syncthreads();
        }
    }

    // --- emit K rows ---
    // layout: boxes[B*K*4] | scores[B*K] | classes[B*K] | suspicion[B*K] | valid[B*K]
    const int OFF_S = BB * KK * 4;
    const int OFF_C = OFF_S + BB * KK;
    const int OFF_U = OFF_C + BB * KK;
    const int OFF_V = OFF_U + BB * KK;
    if (tid < KK) {
        int o = b * KK + tid;
        if (tid < M) {
            unsigned long long key = s_cand[tid];
            float s = __uint_as_float((unsigned int)(key >> 32));
            int a = (int)(((unsigned int)key) ^ 0xFFFFFFFFu);
            float4 bb4 = boxes[(size_t)b * AA + a];
            out[o * 4 + 0] = bb4.x;
            out[o * 4 + 1] = bb4.y;
            out[o * 4 + 2] = bb4.z;
            out[o * 4 + 3] = bb4.w;
            out[OFF_S + o] = s;
            out[OFF_C + o] = (float)g_cls[(size_t)b * AA + a];
            out[OFF_U + o] = g_beta[(size_t)b * AA + a];
            out[OFF_V + o] = 1.0f;
        } else {
            out[o * 4 + 0] = 0.0f;
            out[o * 4 + 1] = 0.0f;
            out[o * 4 + 2] = 0.0f;
            out[o * 4 + 3] = 0.0f;
            out[OFF_S + o] = 0.0f;
            out[OFF_C + o] = 0.0f;
            out[OFF_U + o] = 0.0f;
            out[OFF_V + o] = 0.0f;
        }
    }
}

extern "C" void kernel_launch(void* const* d_in, const int* in_sizes, int n_in,
                              void* d_out, int out_size) {
    const float4* boxes = (const float4*)d_in[0];   // [B, A, 4]
    const float*  obj   = (const float*)d_in[1];    // [B, A]
    const float4* cls   = (const float4*)d_in[2];   // [B, A, C]
    const float*  field = (const float*)d_in[3];    // [B, HF, WF]
    float* out = (float*)d_out;

    int total = BB * AA;
    phase1_kernel<<<(total + 255) / 256, 256>>>(boxes, obj, cls, field);
    phase2_kernel<<<BB, 1024>>>(boxes, out);
}

// round 7
// speedup vs baseline: 1.4187x; 1.4187x over previous
#include <cuda_runtime.h>
#include <cstdint>
#include <math.h>

#define BB 64
#define AA 8400
#define CC 80
#define KK 300
#define HF 160
#define WF 160
#define NBINS 4096
#define CAP 4096
#define THRESH 0.25f
#define FIELD_N (HF * WF)

// scratch (no allocations allowed)
__device__ float g_scores[BB * AA];
__device__ float g_beta[BB * AA];
__device__ int   g_cls[BB * AA];

// ---------------- Kernel A: box-pool beta with field staged in smem ----------------
__global__ __launch_bounds__(1024) void beta_kernel(const float4* __restrict__ boxes,
                                                    const float*  __restrict__ field) {
    extern __shared__ float sfield[];   // 25600 floats = 100KB
    int b = blockIdx.x >> 2;            // 4 blocks per batch
    int part = blockIdx.x & 3;

    const float* f = field + (size_t)b * FIELD_N;
    for (int j = threadIdx.x; j < FIELD_N; j += 1024) sfield[j] = f[j];
    __syncthreads();

    const int a0 = part * (AA / 4);     // 2100 anchors per part
    for (int t = threadIdx.x; t < AA / 4; t += 1024) {
        int a = a0 + t;
        int i = b * AA + a;
        float4 bx = boxes[i];
        float x1 = bx.x, y1 = bx.y, x2 = bx.z, y2 = bx.w;

        float beta = 0.0f;
#pragma unroll
        for (int jy = 0; jy < 3; jy++) {
            float ty = (jy + 0.5f) * (1.0f / 3.0f);
            float ys = y1 + ty * (y2 - y1);
            float v = ys * 0.25f - 0.5f;
            v = fminf(fmaxf(v, 0.0f), (float)(HF - 1));
            float v0f = floorf(v);
            float fv = v - v0f;
            int v0 = (int)v0f;
            int v1 = min(v0 + 1, HF - 1);
#pragma unroll
            for (int jx = 0; jx < 3; jx++) {
                float tx = (jx + 0.5f) * (1.0f / 3.0f);
                float xs = x1 + tx * (x2 - x1);
                float u = xs * 0.25f - 0.5f;
                u = fminf(fmaxf(u, 0.0f), (float)(WF - 1));
                float u0f = floorf(u);
                float fu = u - u0f;
                int u0 = (int)u0f;
                int u1 = min(u0 + 1, WF - 1);
                float f00 = sfield[v0 * WF + u0];
                float f01 = sfield[v0 * WF + u1];
                float f10 = sfield[v1 * WF + u0];
                float f11 = sfield[v1 * WF + u1];
                beta += f00 * (1.0f - fv) * (1.0f - fu)
                      + f01 * (1.0f - fv) * fu
                      + f10 * fv * (1.0f - fu)
                      + f11 * fv * fu;
            }
        }
        beta *= (1.0f / 9.0f);

        float area = fmaxf(x2 - x1, 0.0f) * fmaxf(y2 - y1, 0.0f) * (1.0f / (640.0f * 640.0f));
        g_beta[i] = beta * ((area < 0.01f) ? 1.5f : 1.0f);
    }
}

// ---------------- Kernel B: 4 lanes per anchor, coalesced cls max/argmax ----------------
__global__ __launch_bounds__(256) void score_kernel(const float*  __restrict__ obj,
                                                    const float4* __restrict__ cls) {
    int gw = (blockIdx.x * blockDim.x + threadIdx.x) >> 5;   // global warp
    int lane = threadIdx.x & 31;
    int sub = lane & 3;
    int i = gw * 8 + (lane >> 2);                            // anchor (8 per warp)
    if (i >= BB * AA) return;

    const float4* cp = cls + (size_t)i * (CC / 4);
    float m = -1e30f;
    int am = 0;
#pragma unroll
    for (int k = 0; k < 5; k++) {
        int j = k * 4 + sub;          // lanes of a quad hit contiguous 64B per step
        float4 v4 = cp[j];
        int cb = 4 * j;
        if (v4.x > m) { m = v4.x; am = cb + 0; }
        if (v4.y > m) { m = v4.y; am = cb + 1; }
        if (v4.z > m) { m = v4.z; am = cb + 2; }
        if (v4.w > m) { m = v4.w; am = cb + 3; }
    }
    // combine across the 4 lanes; ties -> lowest class index (matches argmax)
#pragma unroll
    for (int off = 1; off < 4; off <<= 1) {
        float m2 = __shfl_xor_sync(0xffffffffu, m, off);
        int a2 = __shfl_xor_sync(0xffffffffu, am, off);
        if (m2 > m || (m2 == m && a2 < am)) { m = m2; am = a2; }
    }

    if (sub == 0) {
        float bs = g_beta[i];
        float best_cls_score = 1.0f / (1.0f + expf(-(m - 0.5f * bs)));
        float sobj = 1.0f / (1.0f + expf(-(obj[i] - bs)));
        g_scores[i] = sobj * best_cls_score;
        g_cls[i] = am;
    }
}

// ---------------- Phase 2: histogram cutoff + rank-by-counting emit ----------------
__global__ __launch_bounds__(1024) void phase2_kernel(const float4* __restrict__ boxes,
                                                      float* __restrict__ out) {
    int b = blockIdx.x;
    int tid = threadIdx.x;

    __shared__ unsigned long long s_cand[CAP];        // 32KB; first 16KB aliased as histogram
    unsigned int* s_hist = (unsigned int*)s_cand;
    __shared__ unsigned int s_warp[32];
    __shared__ int s_cutoff;
    __shared__ int s_cnt;

    for (int j = tid; j < NBINS; j += 1024) s_hist[j] = 0;
    if (tid == 0) { s_cutoff = 0; s_cnt = 0; }
    __syncthreads();

    const float* sc = g_scores + (size_t)b * AA;
    for (int a = tid; a < AA; a += 1024) {
        float s = sc[a];
        if (s >= THRESH) {
            int bin = (int)((s - THRESH) * (NBINS / 0.75f));
            bin = max(0, min(NBINS - 1, bin));
            atomicAdd(&s_hist[bin], 1u);
        }
    }
    __syncthreads();

    // suffix scan from top bins, find cutoff bin covering rank K
    {
        int g = 1023 - tid;
        int base = 4 * g;
        unsigned int c0 = s_hist[base + 3];
        unsigned int c1 = s_hist[base + 2];
        unsigned int c2 = s_hist[base + 1];
        unsigned int c3 = s_hist[base + 0];
        unsigned int i0 = c0;
        unsigned int i1 = i0 + c1;
        unsigned int i2 = i1 + c2;
        unsigned int i3 = i2 + c3;
        unsigned int ts = i3;

        unsigned int v = ts;
        int lane = tid & 31;
        int w = tid >> 5;
#pragma unroll
        for (int off = 1; off < 32; off <<= 1) {
            unsigned int n = __shfl_up_sync(0xffffffffu, v, off);
            if (lane >= off) v += n;
        }
        if (lane == 31) s_warp[w] = v;
        __syncthreads();
        if (tid < 32) {
            unsigned int x = s_warp[tid];
            unsigned int incl = x;
#pragma unroll
            for (int off = 1; off < 32; off <<= 1) {
                unsigned int n = __shfl_up_sync(0xffffffffu, incl, off);
                if (tid >= off) incl += n;
            }
            s_warp[tid] = incl - x;
        }
        __syncthreads();
        unsigned int texcl = s_warp[w] + (v - ts);

        if (texcl + i0 >= KK) atomicMax(&s_cutoff, base + 3);
        if (texcl + i1 >= KK) atomicMax(&s_cutoff, base + 2);
        if (texcl + i2 >= KK) atomicMax(&s_cutoff, base + 1);
        if (texcl + i3 >= KK) atomicMax(&s_cutoff, base + 0);
    }
    __syncthreads();
    int cutoff = s_cutoff;
    __syncthreads();   // done reading hist before cand overwrites it

    // gather candidates (bin >= cutoff) as packed sort keys
    for (int a = tid; a < AA; a += 1024) {
        float s = sc[a];
        if (s >= THRESH) {
            int bin = (int)((s - THRESH) * (NBINS / 0.75f));
            bin = max(0, min(NBINS - 1, bin));
            if (bin >= cutoff) {
                int p = atomicAdd(&s_cnt, 1);
                if (p < CAP) {
                    unsigned long long key =
                        ((unsigned long long)__float_as_uint(s) << 32) |
                        (unsigned long long)(0xFFFFFFFFu ^ (unsigned int)a);
                    s_cand[p] = key;
                }
            }
        }
    }
    __syncthreads();
    int M = min(s_cnt, CAP);

    // rank-by-counting: keys are unique -> ranks form a permutation of 0..M-1
    const int OFF_S = BB * KK * 4;
    const int OFF_C = OFF_S + BB * KK;
    const int OFF_U = OFF_C + BB * KK;
    const int OFF_V = OFF_U + BB * KK;

    for (int ii = tid; ii < M; ii += 1024) {
        unsigned long long ki = s_cand[ii];
        int rank = 0;
        for (int j = 0; j < M; j++)                 // broadcast LDS reads
            rank += (s_cand[j] > ki) ? 1 : 0;
        if (rank < KK) {
            int o = b * KK + rank;
            float s = __uint_as_float((unsigned int)(ki >> 32));
            int a = (int)(((unsigned int)ki) ^ 0xFFFFFFFFu);
            float4 bb4 = boxes[(size_t)b * AA + a];
            out[o * 4 + 0] = bb4.x;
            out[o * 4 + 1] = bb4.y;
            out[o * 4 + 2] = bb4.z;
            out[o * 4 + 3] = bb4.w;
            out[OFF_S + o] = s;
            out[OFF_C + o] = (float)g_cls[(size_t)b * AA + a];
            out[OFF_U + o] = g_beta[(size_t)b * AA + a];
            out[OFF_V + o] = 1.0f;
        }
    }
    // zero-fill unused slots
    for (int t = tid; t < KK; t += 1024) {
        if (t >= M) {
            int o = b * KK + t;
            out[o * 4 + 0] = 0.0f;
            out[o * 4 + 1] = 0.0f;
            out[o * 4 + 2] = 0.0f;
            out[o * 4 + 3] = 0.0f;
            out[OFF_S + o] = 0.0f;
            out[OFF_C + o] = 0.0f;
            out[OFF_U + o] = 0.0f;
            out[OFF_V + o] = 0.0f;
        }
    }
}

extern "C" void kernel_launch(void* const* d_in, const int* in_sizes, int n_in,
                              void* d_out, int out_size) {
    const float4* boxes = (const float4*)d_in[0];   // [B, A, 4]
    const float*  obj   = (const float*)d_in[1];    // [B, A]
    const float4* cls   = (const float4*)d_in[2];   // [B, A, C]
    const float*  field = (const float*)d_in[3];    // [B, HF, WF]
    float* out = (float*)d_out;

    cudaFuncSetAttribute(beta_kernel, cudaFuncAttributeMaxDynamicSharedMemorySize,
                         FIELD_N * (int)sizeof(float));

    beta_kernel<<<BB * 4, 1024, FIELD_N * sizeof(float)>>>(boxes, field);

    int total_threads = (BB * AA / 8) * 32;          // 4 lanes/anchor, 8 anchors/warp
    score_kernel<<<(total_threads + 255) / 256, 256>>>(obj, cls);

    phase2_kernel<<<BB, 1024>>>(boxes, out);
}